// round 1
// baseline (speedup 1.0000x reference)
#include <cuda_runtime.h>
#include <math.h>

#define Bn 4
#define Tn 8192
#define Dn 512
#define Sn 16
#define PARTS 32   // 128 blocks / 4 batches in the G pass

// Scratch (static device globals — allocation-free per harness rules)
__device__ float g_attn [Bn*Tn*Sn];        // 2 MB
__device__ float g_Gpart[Bn*PARTS*Sn*Dn];  // 4 MB
__device__ float g_G    [Bn*Sn*Dn];
__device__ float g_H    [Bn*Sn*Dn];
__device__ float g_M    [Bn*Sn*Dn];

__device__ __forceinline__ float warp_sum(float v) {
#pragma unroll
    for (int o = 16; o; o >>= 1) v += __shfl_xor_sync(0xffffffffu, v, o);
    return v;
}

// ---------------------------------------------------------------------------
// Kernel 1: attention weights. Grid 128 blocks x 256 thr, 256 tokens/block.
// Each warp processes 4 tokens at a time, lanes split the D dimension.
// ---------------------------------------------------------------------------
__global__ __launch_bounds__(256) void k_attn(const float* __restrict__ x,
                                              const float* __restrict__ centers,
                                              const float* __restrict__ log_scales) {
    __shared__ float4 sc[Sn * 128];          // centers, 32 KB
    __shared__ float s_inv[Sn], s_bias[Sn];

    int tid = threadIdx.x;
    for (int i = tid; i < Sn * 128; i += 256) sc[i] = ((const float4*)centers)[i];
    __syncthreads();
    if (tid < Sn) {
        float c2 = 0.f;
        for (int i = 0; i < 128; i++) {
            float4 c = sc[tid * 128 + i];
            c2 += c.x * c.x + c.y * c.y + c.z * c.z + c.w * c.w;
        }
        float s = expf(log_scales[tid]);
        s = fminf(fmaxf(s, 0.1f), 2.0f);
        float inv = -0.5f / (s * s);
        s_inv[tid]  = inv;
        s_bias[tid] = inv * c2;
    }
    __syncthreads();

    int warp = tid >> 5, lane = tid & 31;
    long long tok0 = (long long)blockIdx.x * 256;
    const float* xb = x + tok0 * Dn;

#pragma unroll 1
    for (int g = 0; g < 8; g++) {
        int tl = warp * 32 + g * 4;          // 4 tokens per iteration
        float acc[4][Sn];
        float x2[4];
#pragma unroll
        for (int i = 0; i < 4; i++) {
            x2[i] = 0.f;
#pragma unroll
            for (int s = 0; s < Sn; s++) acc[i][s] = 0.f;
        }
#pragma unroll
        for (int j = 0; j < 4; j++) {
            int d4 = lane + j * 32;          // float4 index into the 512-wide row
            float4 xv[4];
#pragma unroll
            for (int i = 0; i < 4; i++)
                xv[i] = ((const float4*)(xb + (long long)(tl + i) * Dn))[d4];
#pragma unroll
            for (int i = 0; i < 4; i++)
                x2[i] += xv[i].x * xv[i].x + xv[i].y * xv[i].y +
                         xv[i].z * xv[i].z + xv[i].w * xv[i].w;
#pragma unroll
            for (int s = 0; s < Sn; s++) {
                float4 c = sc[s * 128 + d4];
#pragma unroll
                for (int i = 0; i < 4; i++)
                    acc[i][s] += xv[i].x * c.x + xv[i].y * c.y +
                                 xv[i].z * c.z + xv[i].w * c.w;
            }
        }
#pragma unroll
        for (int i = 0; i < 4; i++) {
            x2[i] = warp_sum(x2[i]);
#pragma unroll
            for (int s = 0; s < Sn; s++) acc[i][s] = warp_sum(acc[i][s]);
        }
        if (lane == 0) {
#pragma unroll
            for (int i = 0; i < 4; i++) {
                float l[Sn];
                float m = -1e30f;
#pragma unroll
                for (int s = 0; s < Sn; s++) {
                    l[s] = s_inv[s] * (x2[i] - 2.f * acc[i][s]) + s_bias[s];
                    m = fmaxf(m, l[s]);
                }
                float sum = 0.f;
#pragma unroll
                for (int s = 0; s < Sn; s++) { l[s] = __expf(l[s] - m); sum += l[s]; }
                float r = 1.f / sum;
                float4* dst = (float4*)(g_attn + (tok0 + tl + i) * Sn);
                dst[0] = make_float4(l[0]*r,  l[1]*r,  l[2]*r,  l[3]*r);
                dst[1] = make_float4(l[4]*r,  l[5]*r,  l[6]*r,  l[7]*r);
                dst[2] = make_float4(l[8]*r,  l[9]*r,  l[10]*r, l[11]*r);
                dst[3] = make_float4(l[12]*r, l[13]*r, l[14]*r, l[15]*r);
            }
        }
    }
}

// ---------------------------------------------------------------------------
// Kernel 2: partial G = attn^T x per 256-token slice. Grid 128 x 256 thr.
// Thread owns the d-pair (2*tid, 2*tid+1); fixed-order token loop (deterministic).
// ---------------------------------------------------------------------------
__global__ __launch_bounds__(256) void k_g(const float* __restrict__ x) {
    __shared__ float s_attn[256 * Sn];       // 16 KB
    int tid = threadIdx.x;
    long long tok0 = (long long)blockIdx.x * 256;

    // coalesced attn tile load: 4096 floats = 1024 float4
    for (int i = tid; i < 1024; i += 256)
        ((float4*)s_attn)[i] = ((const float4*)(g_attn + tok0 * Sn))[i];
    __syncthreads();

    const float* xb = x + tok0 * Dn;
    float2 accG[Sn];
#pragma unroll
    for (int s = 0; s < Sn; s++) { accG[s].x = 0.f; accG[s].y = 0.f; }

#pragma unroll 4
    for (int t = 0; t < 256; t++) {
        float2 xv = ((const float2*)(xb + (long long)t * Dn))[tid];
        const float4* ar = (const float4*)&s_attn[t * Sn];
#pragma unroll
        for (int q = 0; q < 4; q++) {
            float4 a = ar[q];
            accG[q*4+0].x += a.x * xv.x; accG[q*4+0].y += a.x * xv.y;
            accG[q*4+1].x += a.y * xv.x; accG[q*4+1].y += a.y * xv.y;
            accG[q*4+2].x += a.z * xv.x; accG[q*4+2].y += a.z * xv.y;
            accG[q*4+3].x += a.w * xv.x; accG[q*4+3].y += a.w * xv.y;
        }
    }

    int b = (int)(tok0 / Tn);
    int p = (int)((tok0 % Tn) / 256);
    float* gp = g_Gpart + ((b * PARTS + p) * Sn * Dn);
#pragma unroll
    for (int s = 0; s < Sn; s++)
        ((float2*)(gp + s * Dn))[tid] = accG[s];
}

// ---------------------------------------------------------------------------
// Kernel 3: reduce 32 partials -> G. 32768 outputs. Grid 128 x 256 thr.
// ---------------------------------------------------------------------------
__global__ void k_reduce() {
    int idx = blockIdx.x * blockDim.x + threadIdx.x;   // < Bn*Sn*Dn = 32768
    int b = idx >> 13;        // / (Sn*Dn)
    int r = idx & 8191;
    float sum = 0.f;
#pragma unroll
    for (int p = 0; p < PARTS; p++)
        sum += g_Gpart[(b * PARTS + p) * (Sn * Dn) + r];
    g_G[idx] = sum;
}

// ---------------------------------------------------------------------------
// Kernel 4: tiny GEMM out[row][k] = sum_d in[row][d] * W[k][d],
// rows = Bn*Sn = 64 (one block per row), warp-per-k (coalesced W rows).
// stage 0: G * Wv^T -> H ; stage 1: H * Wo^T -> M
// ---------------------------------------------------------------------------
__global__ __launch_bounds__(256) void k_small_gemm(const float* __restrict__ W, int stage) {
    const float* in  = (stage == 0) ? g_G : g_H;
    float*       out = (stage == 0) ? g_H : g_M;
    __shared__ float4 sg[128];               // one 512-float input row
    int tid = threadIdx.x, warp = tid >> 5, lane = tid & 31;
    int row = blockIdx.x;                    // 0..63
    if (tid < 128) sg[tid] = ((const float4*)(in + (long long)row * Dn))[tid];
    __syncthreads();
    for (int k = warp; k < Dn; k += 8) {
        const float4* wr = (const float4*)(W + (long long)k * Dn);
        float p = 0.f;
#pragma unroll
        for (int j = 0; j < 4; j++) {
            int d4 = lane + j * 32;
            float4 w = wr[d4];
            float4 g = sg[d4];
            p += w.x * g.x + w.y * g.y + w.z * g.z + w.w * g.w;
        }
        p = warp_sum(p);
        if (lane == 0) out[(long long)row * Dn + k] = p;
    }
}

// ---------------------------------------------------------------------------
// Kernel 5: y[t,:] = sum_s attn[t,s] * M[b,s,:]. Grid 512 x 256 thr,
// 64 tokens/block; M columns held in registers per thread; float2 stores.
// ---------------------------------------------------------------------------
__global__ __launch_bounds__(256) void k_out(float* __restrict__ y) {
    __shared__ float s_a[64 * Sn];           // 4 KB attn tile
    int tid = threadIdx.x;
    long long tok0 = (long long)blockIdx.x * 64;
    int b = (int)(tok0 / Tn);

    ((float4*)s_a)[tid] = ((const float4*)(g_attn + tok0 * Sn))[tid];  // 256 float4
    __syncthreads();

    const float* Mb = g_M + (long long)b * Sn * Dn;
    float2 m[Sn];
#pragma unroll
    for (int s = 0; s < Sn; s++) m[s] = ((const float2*)(Mb + s * Dn))[tid];

    float* yb = y + tok0 * Dn;
#pragma unroll 2
    for (int t = 0; t < 64; t++) {
        const float4* ar = (const float4*)&s_a[t * Sn];
        float2 o; o.x = 0.f; o.y = 0.f;
#pragma unroll
        for (int q = 0; q < 4; q++) {
            float4 a = ar[q];
            o.x += a.x * m[q*4+0].x + a.y * m[q*4+1].x + a.z * m[q*4+2].x + a.w * m[q*4+3].x;
            o.y += a.x * m[q*4+0].y + a.y * m[q*4+1].y + a.z * m[q*4+2].y + a.w * m[q*4+3].y;
        }
        ((float2*)(yb + (long long)t * Dn))[tid] = o;
    }
}

// ---------------------------------------------------------------------------
extern "C" void kernel_launch(void* const* d_in, const int* in_sizes, int n_in,
                              void* d_out, int out_size) {
    (void)in_sizes; (void)n_in; (void)out_size;
    const float* x          = (const float*)d_in[0];   // [B,T,D]
    const float* centers    = (const float*)d_in[1];   // [S,D]
    const float* log_scales = (const float*)d_in[2];   // [S]
    const float* Wv         = (const float*)d_in[3];   // [D,D]
    const float* Wo         = (const float*)d_in[4];   // [D,D]
    float* y = (float*)d_out;                          // [B,T,D] fp32

    k_attn<<<128, 256>>>(x, centers, log_scales);
    k_g<<<128, 256>>>(x);
    k_reduce<<<128, 256>>>();
    k_small_gemm<<<Bn * Sn, 256>>>(Wv, 0);
    k_small_gemm<<<Bn * Sn, 256>>>(Wo, 1);
    k_out<<<512, 256>>>(y);
}

// round 2
// speedup vs baseline: 1.5676x; 1.5676x over previous
#include <cuda_runtime.h>
#include <math.h>

#define Bn 4
#define Tn 8192
#define Dn 512
#define Sn 16
#define PARTS 64   // 256 blocks / 4 batches in the fused attn+G pass

// Scratch (static device globals — allocation-free per harness rules)
__device__ float g_attn [Bn*Tn*Sn];          // 2 MB
__device__ float g_Gpart[Bn*PARTS*Sn*Dn];    // 8 MB
__device__ float g_G    [Bn*Sn*Dn];
__device__ float g_H    [Bn*Sn*Dn];
__device__ float g_M    [Bn*Sn*Dn];

__device__ __forceinline__ float warp_sum(float v) {
#pragma unroll
    for (int o = 16; o; o >>= 1) v += __shfl_xor_sync(0xffffffffu, v, o);
    return v;
}

// ---------------------------------------------------------------------------
// Kernel 1 (fused): attention weights + partial G = attn^T x.
// Grid 256 blocks x 256 thr, 128 tokens/block.
// Phase 1: warp processes 4 tokens at a time, lanes split D. attn -> smem+gmem.
// Phase 2: thread owns d-pair, fixed-order token loop -> G partial (no atomics).
// ---------------------------------------------------------------------------
__global__ __launch_bounds__(256) void k_attn_g(const float* __restrict__ x,
                                                const float* __restrict__ centers,
                                                const float* __restrict__ log_scales) {
    __shared__ float4 sc[Sn * 128];          // centers, 32 KB
    __shared__ float  s_attn[128 * Sn];      // 8 KB attn tile for phase 2
    __shared__ float  s_inv[Sn], s_bias[Sn];

    int tid = threadIdx.x;
    for (int i = tid; i < Sn * 128; i += 256) sc[i] = ((const float4*)centers)[i];
    __syncthreads();
    if (tid < Sn) {
        float c2 = 0.f;
        for (int i = 0; i < 128; i++) {
            float4 c = sc[tid * 128 + i];
            c2 += c.x * c.x + c.y * c.y + c.z * c.z + c.w * c.w;
        }
        float s = expf(log_scales[tid]);
        s = fminf(fmaxf(s, 0.1f), 2.0f);
        float inv = -0.5f / (s * s);
        s_inv[tid]  = inv;
        s_bias[tid] = inv * c2;
    }
    __syncthreads();

    int warp = tid >> 5, lane = tid & 31;
    long long tok0 = (long long)blockIdx.x * 128;
    const float* xb = x + tok0 * Dn;

    // -------- Phase 1: attn for 128 tokens (each warp: 16 tokens) --------
#pragma unroll 1
    for (int g = 0; g < 4; g++) {
        int tl = warp * 16 + g * 4;          // 4 tokens per iteration
        float acc[4][Sn];
        float x2[4];
#pragma unroll
        for (int i = 0; i < 4; i++) {
            x2[i] = 0.f;
#pragma unroll
            for (int s = 0; s < Sn; s++) acc[i][s] = 0.f;
        }
#pragma unroll
        for (int j = 0; j < 4; j++) {
            int d4 = lane + j * 32;          // float4 index into 512-wide row
            float4 xv[4];
#pragma unroll
            for (int i = 0; i < 4; i++)
                xv[i] = ((const float4*)(xb + (long long)(tl + i) * Dn))[d4];
#pragma unroll
            for (int i = 0; i < 4; i++)
                x2[i] += xv[i].x * xv[i].x + xv[i].y * xv[i].y +
                         xv[i].z * xv[i].z + xv[i].w * xv[i].w;
#pragma unroll
            for (int s = 0; s < Sn; s++) {
                float4 c = sc[s * 128 + d4];
#pragma unroll
                for (int i = 0; i < 4; i++)
                    acc[i][s] += xv[i].x * c.x + xv[i].y * c.y +
                                 xv[i].z * c.z + xv[i].w * c.w;
            }
        }
#pragma unroll
        for (int i = 0; i < 4; i++) {
            x2[i] = warp_sum(x2[i]);
#pragma unroll
            for (int s = 0; s < Sn; s++) acc[i][s] = warp_sum(acc[i][s]);
        }
        if (lane == 0) {
#pragma unroll
            for (int i = 0; i < 4; i++) {
                float l[Sn];
                float m = -1e30f;
#pragma unroll
                for (int s = 0; s < Sn; s++) {
                    l[s] = s_inv[s] * (x2[i] - 2.f * acc[i][s]) + s_bias[s];
                    m = fmaxf(m, l[s]);
                }
                float sum = 0.f;
#pragma unroll
                for (int s = 0; s < Sn; s++) { l[s] = __expf(l[s] - m); sum += l[s]; }
                float r = 1.f / sum;
                float4 v0 = make_float4(l[0]*r,  l[1]*r,  l[2]*r,  l[3]*r);
                float4 v1 = make_float4(l[4]*r,  l[5]*r,  l[6]*r,  l[7]*r);
                float4 v2 = make_float4(l[8]*r,  l[9]*r,  l[10]*r, l[11]*r);
                float4 v3 = make_float4(l[12]*r, l[13]*r, l[14]*r, l[15]*r);
                float4* dg = (float4*)(g_attn + (tok0 + tl + i) * Sn);
                dg[0] = v0; dg[1] = v1; dg[2] = v2; dg[3] = v3;
                float4* ds = (float4*)(s_attn + (tl + i) * Sn);
                ds[0] = v0; ds[1] = v1; ds[2] = v2; ds[3] = v3;
            }
        }
    }
    __syncthreads();

    // -------- Phase 2: G partial over this block's 128 tokens --------
    float2 accG[Sn];
#pragma unroll
    for (int s = 0; s < Sn; s++) { accG[s].x = 0.f; accG[s].y = 0.f; }

#pragma unroll 4
    for (int t = 0; t < 128; t++) {
        float2 xv = ((const float2*)(xb + (long long)t * Dn))[tid];   // d = 2*tid, 2*tid+1
        const float4* ar = (const float4*)&s_attn[t * Sn];
#pragma unroll
        for (int q = 0; q < 4; q++) {
            float4 a = ar[q];
            accG[q*4+0].x += a.x * xv.x; accG[q*4+0].y += a.x * xv.y;
            accG[q*4+1].x += a.y * xv.x; accG[q*4+1].y += a.y * xv.y;
            accG[q*4+2].x += a.z * xv.x; accG[q*4+2].y += a.z * xv.y;
            accG[q*4+3].x += a.w * xv.x; accG[q*4+3].y += a.w * xv.y;
        }
    }

    int b = (int)(tok0 / Tn);
    int p = (int)((tok0 % Tn) / 128);
    float* gp = g_Gpart + ((long long)(b * PARTS + p) * Sn * Dn);
#pragma unroll
    for (int s = 0; s < Sn; s++)
        ((float2*)(gp + s * Dn))[tid] = accG[s];
}

// ---------------------------------------------------------------------------
// Kernel 2: reduce 64 partials -> G. 32768 outputs. Grid 128 x 256 thr.
// ---------------------------------------------------------------------------
__global__ void k_reduce() {
    int idx = blockIdx.x * blockDim.x + threadIdx.x;   // < Bn*Sn*Dn = 32768
    int b = idx >> 13;        // / (Sn*Dn)
    int r = idx & 8191;
    float sum = 0.f;
#pragma unroll
    for (int p = 0; p < PARTS; p++)
        sum += g_Gpart[(long long)(b * PARTS + p) * (Sn * Dn) + r];
    g_G[idx] = sum;
}

// ---------------------------------------------------------------------------
// Kernel 3: small GEMM out[row][k] = sum_d in[row][d] * W[k][d], rows = 64.
// Grid (64 col-chunks, 4 batches) x 256 thr. Block: 16 in-rows in smem (32KB),
// warp w handles column k = kc*8+w across all 16 rows (W loads amortized).
// stage 0: G * Wv^T -> H ; stage 1: H * Wo^T -> M
// ---------------------------------------------------------------------------
__global__ __launch_bounds__(256) void k_small_gemm(const float* __restrict__ W, int stage) {
    const float* in  = (stage == 0) ? g_G : g_H;
    float*       out = (stage == 0) ? g_H : g_M;
    __shared__ float4 s_in[16 * 128];        // 16 rows x 512 floats = 32 KB

    int tid = threadIdx.x, warp = tid >> 5, lane = tid & 31;
    int kc = blockIdx.x;                     // 0..63 column chunk
    int b  = blockIdx.y;                     // 0..3 batch

    const float4* src = (const float4*)(in + (long long)b * 16 * Dn);
#pragma unroll
    for (int i = 0; i < 8; i++) s_in[tid + i * 256] = src[tid + i * 256];
    __syncthreads();

    int k = kc * 8 + warp;                   // output column, 0..511
    const float4* wr = (const float4*)(W + (long long)k * Dn);
    float4 w0 = wr[lane], w1 = wr[lane + 32], w2 = wr[lane + 64], w3 = wr[lane + 96];

    float acc[16];
#pragma unroll
    for (int r = 0; r < 16; r++) {
        float4 g0 = s_in[r * 128 + lane];
        float4 g1 = s_in[r * 128 + lane + 32];
        float4 g2 = s_in[r * 128 + lane + 64];
        float4 g3 = s_in[r * 128 + lane + 96];
        acc[r] = w0.x*g0.x + w0.y*g0.y + w0.z*g0.z + w0.w*g0.w
               + w1.x*g1.x + w1.y*g1.y + w1.z*g1.z + w1.w*g1.w
               + w2.x*g2.x + w2.y*g2.y + w2.z*g2.z + w2.w*g2.w
               + w3.x*g3.x + w3.y*g3.y + w3.z*g3.z + w3.w*g3.w;
    }
#pragma unroll
    for (int r = 0; r < 16; r++) acc[r] = warp_sum(acc[r]);
    if (lane < 16)
        out[(long long)(b * 16 + lane) * Dn + k] = acc[lane];  // needs acc[r] on all lanes: butterfly gives that
}

// ---------------------------------------------------------------------------
// Kernel 4: y[t,:] = sum_s attn[t,s] * M[b,s,:]. Grid 512 x 256 thr,
// 64 tokens/block; M columns held in registers per thread; float2 stores.
// ---------------------------------------------------------------------------
__global__ __launch_bounds__(256) void k_out(float* __restrict__ y) {
    __shared__ float s_a[64 * Sn];           // 4 KB attn tile
    int tid = threadIdx.x;
    long long tok0 = (long long)blockIdx.x * 64;
    int b = (int)(tok0 / Tn);

    ((float4*)s_a)[tid] = ((const float4*)(g_attn + tok0 * Sn))[tid];  // 256 float4
    __syncthreads();

    const float* Mb = g_M + (long long)b * Sn * Dn;
    float2 m[Sn];
#pragma unroll
    for (int s = 0; s < Sn; s++) m[s] = ((const float2*)(Mb + s * Dn))[tid];

    float* yb = y + tok0 * Dn;
#pragma unroll 2
    for (int t = 0; t < 64; t++) {
        const float4* ar = (const float4*)&s_a[t * Sn];
        float2 o; o.x = 0.f; o.y = 0.f;
#pragma unroll
        for (int q = 0; q < 4; q++) {
            float4 a = ar[q];
            o.x += a.x * m[q*4+0].x + a.y * m[q*4+1].x + a.z * m[q*4+2].x + a.w * m[q*4+3].x;
            o.y += a.x * m[q*4+0].y + a.y * m[q*4+1].y + a.z * m[q*4+2].y + a.w * m[q*4+3].y;
        }
        ((float2*)(yb + (long long)t * Dn))[tid] = o;
    }
}

// ---------------------------------------------------------------------------
extern "C" void kernel_launch(void* const* d_in, const int* in_sizes, int n_in,
                              void* d_out, int out_size) {
    (void)in_sizes; (void)n_in; (void)out_size;
    const float* x          = (const float*)d_in[0];   // [B,T,D]
    const float* centers    = (const float*)d_in[1];   // [S,D]
    const float* log_scales = (const float*)d_in[2];   // [S]
    const float* Wv         = (const float*)d_in[3];   // [D,D]
    const float* Wo         = (const float*)d_in[4];   // [D,D]
    float* y = (float*)d_out;                          // [B,T,D] fp32

    k_attn_g<<<256, 256>>>(x, centers, log_scales);
    k_reduce<<<128, 256>>>();
    k_small_gemm<<<dim3(64, 4), 256>>>(Wv, 0);
    k_small_gemm<<<dim3(64, 4), 256>>>(Wo, 1);
    k_out<<<512, 256>>>(y);
}